// round 1
// baseline (speedup 1.0000x reference)
#include <cuda_runtime.h>
#include <math.h>

// Problem constants
#define CC   128     // residual channels (= skip channels)
#define SS   128
#define TLEN 8192
#define BB   2
#define LL   20
#define TT   128     // time tile per block
#define KC   8       // k-chunk
#define NCHUNK (CC / KC)

#define SMEM_BYTES ((3 * CC * TT + 2 * KC * CC) * 4)

// -------- device scratch (no allocations allowed) --------
__device__ float g_h0[BB * CC * TLEN];
__device__ float g_h1[BB * CC * TLEN];
__device__ float g_w0T[LL * CC * CC];   // [l][k][o] of w_dil[..,..,0]
__device__ float g_w1T[LL * CC * CC];   // [l][k][o] of w_dil[..,..,1]
__device__ float g_wtT[LL * CC * CC];
__device__ float g_wsT[LL * CC * CC];
__device__ float g_wkT[LL * CC * CC];

// -------- weight transpose: [l][o][c] -> [l][c][o] --------
__global__ void transpose_weights(const float* __restrict__ w_dil,
                                  const float* __restrict__ w_tanh,
                                  const float* __restrict__ w_sig,
                                  const float* __restrict__ w_skip)
{
    int idx = blockIdx.x * blockDim.x + threadIdx.x;
    if (idx >= LL * CC * CC) return;
    int o = idx & (CC - 1);
    int c = (idx >> 7) & (CC - 1);
    int l = idx >> 14;
    size_t src = ((size_t)l * CC + o) * CC + c;
    g_w0T[idx] = w_dil[src * 2 + 0];
    g_w1T[idx] = w_dil[src * 2 + 1];
    g_wtT[idx] = w_tanh[src];
    g_wsT[idx] = w_sig[src];
    g_wkT[idx] = w_skip[src];
}

// -------- input 1x1 conv (IN_CH = 1): h0[b][c][t] = w_in[c]*x[b][t] + b_in[c] --------
__global__ void input_conv(const float* __restrict__ x,
                           const float* __restrict__ w_in,
                           const float* __restrict__ b_in)
{
    int i4 = blockIdx.x * blockDim.x + threadIdx.x;
    if (i4 >= BB * CC * TLEN / 4) return;
    int t4 = i4 & (TLEN / 4 - 1);
    int c  = (i4 >> 11) & (CC - 1);
    int b  = i4 >> 18;
    float w  = w_in[c];
    float bv = b_in[c];
    float4 xv = ((const float4*)x)[(size_t)b * (TLEN / 4) + t4];
    float4 h;
    h.x = fmaf(w, xv.x, bv);
    h.y = fmaf(w, xv.y, bv);
    h.z = fmaf(w, xv.z, bv);
    h.w = fmaf(w, xv.w, bv);
    ((float4*)g_h0)[i4] = h;
}

// -------- GEMM pass: acc[8][8] += wT(128x128, [k][o]) * Bb(smem [k][t]) --------
__device__ __forceinline__ void gemm_pass(const float* __restrict__ wT,
                                          const float* __restrict__ Bb,
                                          float* __restrict__ sW,
                                          float acc[8][8], int tid)
{
    const int tx = tid & 15;
    const int ty = tid >> 4;
    const int lk = tid >> 5;            // 0..7
    const int lo = (tid & 31) << 2;     // 0..124
    // preload chunk 0 into buffer 0
    *(float4*)(sW + lk * CC + lo) = __ldg((const float4*)(wT + lk * CC + lo));
#pragma unroll 1
    for (int ch = 0; ch < NCHUNK; ++ch) {
        __syncthreads();
        if (ch + 1 < NCHUNK) {
            *(float4*)(sW + ((ch + 1) & 1) * (KC * CC) + lk * CC + lo) =
                __ldg((const float4*)(wT + (ch + 1) * (KC * CC) + lk * CC + lo));
        }
        const float* Wc = sW + (ch & 1) * (KC * CC);
        const float* Bc = Bb + ch * KC * TT;
#pragma unroll
        for (int kk = 0; kk < KC; ++kk) {
            float4 a0 = *(const float4*)(Wc + kk * CC + tx * 4);
            float4 a1 = *(const float4*)(Wc + kk * CC + 64 + tx * 4);
            float4 b0 = *(const float4*)(Bc + kk * TT + ty * 4);
            float4 b1 = *(const float4*)(Bc + kk * TT + 64 + ty * 4);
            float av[8] = {a0.x, a0.y, a0.z, a0.w, a1.x, a1.y, a1.z, a1.w};
            float bv[8] = {b0.x, b0.y, b0.z, b0.w, b1.x, b1.y, b1.z, b1.w};
#pragma unroll
            for (int i = 0; i < 8; ++i)
#pragma unroll
                for (int j = 0; j < 8; ++j)
                    acc[i][j] = fmaf(av[i], bv[j], acc[i][j]);
        }
    }
}

__device__ __forceinline__ float sigmoidf_fast(float v)
{
    return 1.0f / (1.0f + __expf(-v));
}

// -------- fused layer kernel --------
__global__ void __launch_bounds__(256, 1)
layer_kernel(int layer, int dil, int ping,
             const float* __restrict__ b_dil, const float* __restrict__ b_tanh,
             const float* __restrict__ b_sig, const float* __restrict__ b_skip,
             float* __restrict__ out_base)
{
    extern __shared__ float smem[];
    float* bufA = smem;                 // h_cur, later filt
    float* bufB = bufA + CC * TT;       // h_del, later x_h
    float* bufC = bufB + CC * TT;       // x_dil
    float* sW   = bufC + CC * TT;       // [2][KC][CC] weight chunks

    const float* hin  = ping ? g_h1 : g_h0;
    float*       hout = ping ? g_h0 : g_h1;

    const int tid = threadIdx.x;
    const int blk = blockIdx.x;         // 0..127
    const int b   = blk >> 6;           // 64 tiles per sample
    const int t0  = (blk & 63) * TT;

    const float* hbase = hin + (size_t)b * CC * TLEN;
    float* outputs = out_base + ((size_t)layer * BB + b) * CC * TLEN;
    float* skips   = out_base + (size_t)LL * BB * CC * TLEN
                              + ((size_t)layer * BB + b) * SS * TLEN;

    // ---- load h_cur tile (-> bufA, and fused copy to outputs), h_del tile (-> bufB)
    const bool aligned = (dil & 3) == 0;
#pragma unroll
    for (int it = 0; it < 16; ++it) {
        int idx = tid + it * 256;           // float4 slot in 128x128 tile
        int c   = idx >> 5;
        int c4  = (idx & 31) << 2;
        const float* src = hbase + (size_t)c * TLEN + t0 + c4;
        float4 v = *(const float4*)src;
        *(float4*)(bufA + c * TT + c4) = v;
        *(float4*)(outputs + (size_t)c * TLEN + t0 + c4) = v;
        int td = t0 + c4 - dil;
        float4 vd;
        if (td >= 0 && aligned) {
            vd = *(const float4*)(hbase + (size_t)c * TLEN + td);
        } else {
            float e[4];
#pragma unroll
            for (int j = 0; j < 4; ++j) {
                int t = td + j;
                e[j] = (t >= 0) ? hbase[(size_t)c * TLEN + t] : 0.0f;
            }
            vd = make_float4(e[0], e[1], e[2], e[3]);
        }
        *(float4*)(bufB + c * TT + c4) = vd;
    }
    // visibility handled by first __syncthreads inside gemm_pass

    const int tx = tid & 15, ty = tid >> 4;
    const int oL = tx * 4, tL = ty * 4;
    float acc[8][8];

    // ---- GEMM1: x_dil = w0 @ h_del + w1 @ h_cur + b_dil  -> bufC
    {
        const float* bd = b_dil + layer * CC;
#pragma unroll
        for (int i = 0; i < 8; ++i) {
            float bv = bd[oL + (i & 3) + ((i >> 2) << 6)];
#pragma unroll
            for (int j = 0; j < 8; ++j) acc[i][j] = bv;
        }
        gemm_pass(g_w0T + (size_t)layer * CC * CC, bufB, sW, acc, tid);
        gemm_pass(g_w1T + (size_t)layer * CC * CC, bufA, sW, acc, tid);
#pragma unroll
        for (int i = 0; i < 8; ++i) {
            int o = oL + (i & 3) + ((i >> 2) << 6);
            *(float4*)(bufC + o * TT + tL)      = make_float4(acc[i][0], acc[i][1], acc[i][2], acc[i][3]);
            *(float4*)(bufC + o * TT + 64 + tL) = make_float4(acc[i][4], acc[i][5], acc[i][6], acc[i][7]);
        }
    }

    // ---- GEMM2: filt = tanh(w_tanh @ x_dil + b_tanh) -> bufA
    {
        const float* bd = b_tanh + layer * CC;
#pragma unroll
        for (int i = 0; i < 8; ++i) {
            float bv = bd[oL + (i & 3) + ((i >> 2) << 6)];
#pragma unroll
            for (int j = 0; j < 8; ++j) acc[i][j] = bv;
        }
        gemm_pass(g_wtT + (size_t)layer * CC * CC, bufC, sW, acc, tid);
#pragma unroll
        for (int i = 0; i < 8; ++i) {
            int o = oL + (i & 3) + ((i >> 2) << 6);
#pragma unroll
            for (int j = 0; j < 8; ++j) {
                int t = tL + (j & 3) + ((j >> 2) << 6);
                bufA[o * TT + t] = tanhf(acc[i][j]);
            }
        }
    }

    // ---- GEMM3: gate; x_h = sigmoid(gate)*filt -> bufB; h_next = x_h + x_dil -> global
    {
        const float* bd = b_sig + layer * CC;
#pragma unroll
        for (int i = 0; i < 8; ++i) {
            float bv = bd[oL + (i & 3) + ((i >> 2) << 6)];
#pragma unroll
            for (int j = 0; j < 8; ++j) acc[i][j] = bv;
        }
        gemm_pass(g_wsT + (size_t)layer * CC * CC, bufC, sW, acc, tid);
        float* hob = hout + (size_t)b * CC * TLEN;
#pragma unroll
        for (int i = 0; i < 8; ++i) {
            int o = oL + (i & 3) + ((i >> 2) << 6);
            float xh[8];
#pragma unroll
            for (int j = 0; j < 8; ++j) {
                int t = tL + (j & 3) + ((j >> 2) << 6);
                float g = sigmoidf_fast(acc[i][j]);
                xh[j] = g * bufA[o * TT + t];
                bufB[o * TT + t] = xh[j];
            }
            float4 h0 = make_float4(xh[0] + bufC[o * TT + tL + 0],
                                    xh[1] + bufC[o * TT + tL + 1],
                                    xh[2] + bufC[o * TT + tL + 2],
                                    xh[3] + bufC[o * TT + tL + 3]);
            float4 h1 = make_float4(xh[4] + bufC[o * TT + 64 + tL + 0],
                                    xh[5] + bufC[o * TT + 64 + tL + 1],
                                    xh[6] + bufC[o * TT + 64 + tL + 2],
                                    xh[7] + bufC[o * TT + 64 + tL + 3]);
            *(float4*)(hob + (size_t)o * TLEN + t0 + tL)      = h0;
            *(float4*)(hob + (size_t)o * TLEN + t0 + 64 + tL) = h1;
        }
    }

    // ---- GEMM4: skip = w_skip @ x_h + b_skip -> global
    {
        const float* bd = b_skip + layer * SS;
#pragma unroll
        for (int i = 0; i < 8; ++i) {
            float bv = bd[oL + (i & 3) + ((i >> 2) << 6)];
#pragma unroll
            for (int j = 0; j < 8; ++j) acc[i][j] = bv;
        }
        gemm_pass(g_wkT + (size_t)layer * CC * CC, bufB, sW, acc, tid);
#pragma unroll
        for (int i = 0; i < 8; ++i) {
            int o = oL + (i & 3) + ((i >> 2) << 6);
            *(float4*)(skips + (size_t)o * TLEN + t0 + tL) =
                make_float4(acc[i][0], acc[i][1], acc[i][2], acc[i][3]);
            *(float4*)(skips + (size_t)o * TLEN + t0 + 64 + tL) =
                make_float4(acc[i][4], acc[i][5], acc[i][6], acc[i][7]);
        }
    }
}

// -------- host orchestration --------
extern "C" void kernel_launch(void* const* d_in, const int* in_sizes, int n_in,
                              void* d_out, int out_size)
{
    const float* x      = (const float*)d_in[0];
    const float* w_in   = (const float*)d_in[1];
    const float* b_in   = (const float*)d_in[2];
    const float* w_dil  = (const float*)d_in[3];
    const float* b_dil  = (const float*)d_in[4];
    const float* w_tanh = (const float*)d_in[5];
    const float* b_tanh = (const float*)d_in[6];
    const float* w_sig  = (const float*)d_in[7];
    const float* b_sig  = (const float*)d_in[8];
    const float* w_skip = (const float*)d_in[9];
    const float* b_skip = (const float*)d_in[10];
    float* out = (float*)d_out;

    cudaFuncSetAttribute(layer_kernel,
                         cudaFuncAttributeMaxDynamicSharedMemorySize, SMEM_BYTES);

    transpose_weights<<<(LL * CC * CC + 255) / 256, 256>>>(w_dil, w_tanh, w_sig, w_skip);
    input_conv<<<(BB * CC * TLEN / 4 + 255) / 256, 256>>>(x, w_in, b_in);

    const int dils[LL] = {1, 2, 4, 8, 16, 32, 64, 128, 256, 512,
                          1, 2, 4, 8, 16, 32, 64, 128, 256, 512};
    for (int i = 0; i < LL; ++i) {
        layer_kernel<<<(BB * TLEN) / TT, 256, SMEM_BYTES>>>(
            i, dils[i], i & 1, b_dil, b_tanh, b_sig, b_skip, out);
    }
}

// round 2
// speedup vs baseline: 1.1650x; 1.1650x over previous
#include <cuda_runtime.h>
#include <math.h>

// Problem constants
#define CC   128     // residual channels (= skip channels)
#define SS   128
#define TLEN 8192
#define BB   2
#define LL   20
#define TT   128     // time tile per block
#define KC   16      // k-chunk
#define NCHUNK (CC / KC)

#define SMEM_BYTES ((3 * CC * TT + 2 * KC * CC) * 4)

typedef unsigned long long u64;

// -------- f32x2 packed helpers (sm_103a) --------
__device__ __forceinline__ u64 dup2(float v) {
    u64 r; unsigned u = __float_as_uint(v);
    asm("mov.b64 %0, {%1, %1};" : "=l"(r) : "r"(u));
    return r;
}
__device__ __forceinline__ u64 pack2(float lo, float hi) {
    u64 r; unsigned a = __float_as_uint(lo), b = __float_as_uint(hi);
    asm("mov.b64 %0, {%1, %2};" : "=l"(r) : "r"(a), "r"(b));
    return r;
}
__device__ __forceinline__ void unpack2(u64 v, float& lo, float& hi) {
    unsigned a, b;
    asm("mov.b64 {%0, %1}, %2;" : "=r"(a), "=r"(b) : "l"(v));
    lo = __uint_as_float(a); hi = __uint_as_float(b);
}
__device__ __forceinline__ void ffma2(u64& d, u64 a, u64 b) {
    asm("fma.rn.f32x2 %0, %1, %2, %0;" : "+l"(d) : "l"(a), "l"(b));
}

// -------- device scratch (no allocations allowed) --------
__device__ float g_h0[BB * CC * TLEN];
__device__ float g_h1[BB * CC * TLEN];
__device__ float g_w0T[LL * CC * CC];   // [l][k][o] of w_dil[..,..,0]
__device__ float g_w1T[LL * CC * CC];   // [l][k][o] of w_dil[..,..,1]
__device__ float g_wtT[LL * CC * CC];
__device__ float g_wsT[LL * CC * CC];
__device__ float g_wkT[LL * CC * CC];

// -------- weight transpose: [l][o][c] -> [l][c][o] --------
__global__ void transpose_weights(const float* __restrict__ w_dil,
                                  const float* __restrict__ w_tanh,
                                  const float* __restrict__ w_sig,
                                  const float* __restrict__ w_skip)
{
    int idx = blockIdx.x * blockDim.x + threadIdx.x;
    if (idx >= LL * CC * CC) return;
    int o = idx & (CC - 1);
    int c = (idx >> 7) & (CC - 1);
    int l = idx >> 14;
    size_t src = ((size_t)l * CC + o) * CC + c;
    g_w0T[idx] = w_dil[src * 2 + 0];
    g_w1T[idx] = w_dil[src * 2 + 1];
    g_wtT[idx] = w_tanh[src];
    g_wsT[idx] = w_sig[src];
    g_wkT[idx] = w_skip[src];
}

// -------- input 1x1 conv (IN_CH = 1) --------
__global__ void input_conv(const float* __restrict__ x,
                           const float* __restrict__ w_in,
                           const float* __restrict__ b_in)
{
    int i4 = blockIdx.x * blockDim.x + threadIdx.x;
    if (i4 >= BB * CC * TLEN / 4) return;
    int t4 = i4 & (TLEN / 4 - 1);
    int c  = (i4 >> 11) & (CC - 1);
    int b  = i4 >> 18;
    float w  = w_in[c];
    float bv = b_in[c];
    float4 xv = ((const float4*)x)[(size_t)b * (TLEN / 4) + t4];
    float4 h;
    h.x = fmaf(w, xv.x, bv);
    h.y = fmaf(w, xv.y, bv);
    h.z = fmaf(w, xv.z, bv);
    h.w = fmaf(w, xv.w, bv);
    ((float4*)g_h0)[i4] = h;
}

// -------- GEMM pass (f32x2): acc2[4][8] pairs over o --------
// acc2[p][j]: p -> o pair base: p0:oL, p1:oL+2, p2:64+oL, p3:64+oL+2 (lo = even o)
//             j -> t: j0..3 = tL+j, j4..7 = 64+tL+(j-4)
__device__ __forceinline__ void gemm_pass(const float* __restrict__ wT,
                                          const float* __restrict__ Bb,
                                          float* __restrict__ sW,
                                          u64 acc[4][8], int tid)
{
    const int tx = tid & 15;
    const int ty = tid >> 4;
    // preload chunk 0 into buffer 0 (KC*CC floats = 512 float4 slots, 2/thread)
    {
        int s0 = tid, s1 = tid + 256;
        *(float4*)(sW + (s0 >> 5) * CC + ((s0 & 31) << 2)) =
            __ldg((const float4*)(wT + (s0 >> 5) * CC + ((s0 & 31) << 2)));
        *(float4*)(sW + (s1 >> 5) * CC + ((s1 & 31) << 2)) =
            __ldg((const float4*)(wT + (s1 >> 5) * CC + ((s1 & 31) << 2)));
    }
#pragma unroll 1
    for (int ch = 0; ch < NCHUNK; ++ch) {
        __syncthreads();
        if (ch + 1 < NCHUNK) {
            const float* src = wT + (ch + 1) * (KC * CC);
            float* dst = sW + ((ch + 1) & 1) * (KC * CC);
            int s0 = tid, s1 = tid + 256;
            *(float4*)(dst + (s0 >> 5) * CC + ((s0 & 31) << 2)) =
                __ldg((const float4*)(src + (s0 >> 5) * CC + ((s0 & 31) << 2)));
            *(float4*)(dst + (s1 >> 5) * CC + ((s1 & 31) << 2)) =
                __ldg((const float4*)(src + (s1 >> 5) * CC + ((s1 & 31) << 2)));
        }
        const float* Wc = sW + (ch & 1) * (KC * CC);
        const float* Bc = Bb + ch * KC * TT;
#pragma unroll
        for (int kk = 0; kk < KC; ++kk) {
            ulonglong2 A0 = *(const ulonglong2*)(Wc + kk * CC + tx * 4);
            ulonglong2 A1 = *(const ulonglong2*)(Wc + kk * CC + 64 + tx * 4);
            float4 b0 = *(const float4*)(Bc + kk * TT + ty * 4);
            float4 b1 = *(const float4*)(Bc + kk * TT + 64 + ty * 4);
            u64 bd[8];
            bd[0] = dup2(b0.x); bd[1] = dup2(b0.y); bd[2] = dup2(b0.z); bd[3] = dup2(b0.w);
            bd[4] = dup2(b1.x); bd[5] = dup2(b1.y); bd[6] = dup2(b1.z); bd[7] = dup2(b1.w);
            u64 ap[4];
            ap[0] = A0.x; ap[1] = A0.y; ap[2] = A1.x; ap[3] = A1.y;
#pragma unroll
            for (int p = 0; p < 4; ++p)
#pragma unroll
                for (int j = 0; j < 8; ++j)
                    ffma2(acc[p][j], ap[p], bd[j]);
        }
    }
}

__device__ __forceinline__ float sigmoidf_fast(float v)
{
    return 1.0f / (1.0f + __expf(-v));
}
__device__ __forceinline__ float tanhf_fast(float v)
{
    float a = fabsf(v);
    float e = __expf(-2.0f * a);           // in (0,1], no overflow
    float t = (1.0f - e) / (1.0f + e);
    return copysignf(t, v);
}

// helper: o pair base for p
__device__ __forceinline__ int opair(int p, int oL)
{
    return oL + ((p & 1) << 1) + ((p >> 1) << 6);
}

// -------- fused layer kernel --------
__global__ void __launch_bounds__(256, 1)
layer_kernel(int layer, int dil, int ping,
             const float* __restrict__ b_dil, const float* __restrict__ b_tanh,
             const float* __restrict__ b_sig, const float* __restrict__ b_skip,
             float* __restrict__ out_base)
{
    extern __shared__ float smem[];
    float* bufA = smem;                 // h_cur, later filt
    float* bufB = bufA + CC * TT;       // h_del, later x_h
    float* bufC = bufB + CC * TT;       // x_dil
    float* sW   = bufC + CC * TT;       // [2][KC][CC] weight chunks

    const float* hin  = ping ? g_h1 : g_h0;
    float*       hout = ping ? g_h0 : g_h1;

    const int tid = threadIdx.x;
    const int blk = blockIdx.x;         // 0..127
    const int b   = blk >> 6;           // 64 tiles per sample
    const int t0  = (blk & 63) * TT;

    const float* hbase = hin + (size_t)b * CC * TLEN;
    float* outputs = out_base + ((size_t)layer * BB + b) * CC * TLEN;
    float* skips   = out_base + (size_t)LL * BB * CC * TLEN
                              + ((size_t)layer * BB + b) * SS * TLEN;

    // ---- load h_cur tile (-> bufA, fused copy to outputs), h_del tile (-> bufB)
    const bool aligned = (dil & 3) == 0;
#pragma unroll
    for (int it = 0; it < 16; ++it) {
        int idx = tid + it * 256;           // float4 slot in 128x128 tile
        int c   = idx >> 5;
        int c4  = (idx & 31) << 2;
        const float* src = hbase + (size_t)c * TLEN + t0 + c4;
        float4 v = *(const float4*)src;
        *(float4*)(bufA + c * TT + c4) = v;
        *(float4*)(outputs + (size_t)c * TLEN + t0 + c4) = v;
        int td = t0 + c4 - dil;
        float4 vd;
        if (td >= 0 && aligned) {
            vd = *(const float4*)(hbase + (size_t)c * TLEN + td);
        } else {
            float e[4];
#pragma unroll
            for (int j = 0; j < 4; ++j) {
                int t = td + j;
                e[j] = (t >= 0) ? hbase[(size_t)c * TLEN + t] : 0.0f;
            }
            vd = make_float4(e[0], e[1], e[2], e[3]);
        }
        *(float4*)(bufB + c * TT + c4) = vd;
    }
    // visibility handled by first __syncthreads inside gemm_pass

    const int tx = tid & 15, ty = tid >> 4;
    const int oL = tx * 4, tL = ty * 4;
    u64 acc[4][8];

    // ---- GEMM1: x_dil = w0 @ h_del + w1 @ h_cur + b_dil  -> bufC
    {
        const float* bd = b_dil + layer * CC;
#pragma unroll
        for (int p = 0; p < 4; ++p) {
            int o0 = opair(p, oL);
            u64 bb = pack2(bd[o0], bd[o0 + 1]);
#pragma unroll
            for (int j = 0; j < 8; ++j) acc[p][j] = bb;
        }
        gemm_pass(g_w0T + (size_t)layer * CC * CC, bufB, sW, acc, tid);
        gemm_pass(g_w1T + (size_t)layer * CC * CC, bufA, sW, acc, tid);
#pragma unroll
        for (int p = 0; p < 4; ++p) {
            int o0 = opair(p, oL);
            float lo[8], hi[8];
#pragma unroll
            for (int j = 0; j < 8; ++j) unpack2(acc[p][j], lo[j], hi[j]);
            *(float4*)(bufC + o0 * TT + tL)            = make_float4(lo[0], lo[1], lo[2], lo[3]);
            *(float4*)(bufC + o0 * TT + 64 + tL)       = make_float4(lo[4], lo[5], lo[6], lo[7]);
            *(float4*)(bufC + (o0 + 1) * TT + tL)      = make_float4(hi[0], hi[1], hi[2], hi[3]);
            *(float4*)(bufC + (o0 + 1) * TT + 64 + tL) = make_float4(hi[4], hi[5], hi[6], hi[7]);
        }
    }

    // ---- GEMM2: filt = tanh(w_tanh @ x_dil + b_tanh) -> bufA
    {
        const float* bd = b_tanh + layer * CC;
#pragma unroll
        for (int p = 0; p < 4; ++p) {
            int o0 = opair(p, oL);
            u64 bb = pack2(bd[o0], bd[o0 + 1]);
#pragma unroll
            for (int j = 0; j < 8; ++j) acc[p][j] = bb;
        }
        gemm_pass(g_wtT + (size_t)layer * CC * CC, bufC, sW, acc, tid);
#pragma unroll
        for (int p = 0; p < 4; ++p) {
            int o0 = opair(p, oL);
            float lo[8], hi[8];
#pragma unroll
            for (int j = 0; j < 8; ++j) {
                unpack2(acc[p][j], lo[j], hi[j]);
                lo[j] = tanhf_fast(lo[j]);
                hi[j] = tanhf_fast(hi[j]);
            }
            *(float4*)(bufA + o0 * TT + tL)            = make_float4(lo[0], lo[1], lo[2], lo[3]);
            *(float4*)(bufA + o0 * TT + 64 + tL)       = make_float4(lo[4], lo[5], lo[6], lo[7]);
            *(float4*)(bufA + (o0 + 1) * TT + tL)      = make_float4(hi[0], hi[1], hi[2], hi[3]);
            *(float4*)(bufA + (o0 + 1) * TT + 64 + tL) = make_float4(hi[4], hi[5], hi[6], hi[7]);
        }
    }

    // ---- GEMM3: gate; x_h = sigmoid(gate)*filt -> bufB; h_next = x_h + x_dil -> global
    {
        const float* bd = b_sig + layer * CC;
#pragma unroll
        for (int p = 0; p < 4; ++p) {
            int o0 = opair(p, oL);
            u64 bb = pack2(bd[o0], bd[o0 + 1]);
#pragma unroll
            for (int j = 0; j < 8; ++j) acc[p][j] = bb;
        }
        gemm_pass(g_wsT + (size_t)layer * CC * CC, bufC, sW, acc, tid);
        float* hob = hout + (size_t)b * CC * TLEN;
#pragma unroll
        for (int p = 0; p < 4; ++p) {
            int o0 = opair(p, oL);
            float lo[8], hi[8];
#pragma unroll
            for (int j = 0; j < 8; ++j) unpack2(acc[p][j], lo[j], hi[j]);
#pragma unroll
            for (int r = 0; r < 2; ++r) {
                int o = o0 + r;
                const float* g8 = r ? hi : lo;
                float4 f0 = *(const float4*)(bufA + o * TT + tL);
                float4 f1 = *(const float4*)(bufA + o * TT + 64 + tL);
                float xh[8];
                xh[0] = sigmoidf_fast(g8[0]) * f0.x;
                xh[1] = sigmoidf_fast(g8[1]) * f0.y;
                xh[2] = sigmoidf_fast(g8[2]) * f0.z;
                xh[3] = sigmoidf_fast(g8[3]) * f0.w;
                xh[4] = sigmoidf_fast(g8[4]) * f1.x;
                xh[5] = sigmoidf_fast(g8[5]) * f1.y;
                xh[6] = sigmoidf_fast(g8[6]) * f1.z;
                xh[7] = sigmoidf_fast(g8[7]) * f1.w;
                *(float4*)(bufB + o * TT + tL)      = make_float4(xh[0], xh[1], xh[2], xh[3]);
                *(float4*)(bufB + o * TT + 64 + tL) = make_float4(xh[4], xh[5], xh[6], xh[7]);
                float4 c0 = *(const float4*)(bufC + o * TT + tL);
                float4 c1 = *(const float4*)(bufC + o * TT + 64 + tL);
                *(float4*)(hob + (size_t)o * TLEN + t0 + tL) =
                    make_float4(xh[0] + c0.x, xh[1] + c0.y, xh[2] + c0.z, xh[3] + c0.w);
                *(float4*)(hob + (size_t)o * TLEN + t0 + 64 + tL) =
                    make_float4(xh[4] + c1.x, xh[5] + c1.y, xh[6] + c1.z, xh[7] + c1.w);
            }
        }
    }

    // ---- GEMM4: skip = w_skip @ x_h + b_skip -> global
    {
        const float* bd = b_skip + layer * SS;
#pragma unroll
        for (int p = 0; p < 4; ++p) {
            int o0 = opair(p, oL);
            u64 bb = pack2(bd[o0], bd[o0 + 1]);
#pragma unroll
            for (int j = 0; j < 8; ++j) acc[p][j] = bb;
        }
        gemm_pass(g_wkT + (size_t)layer * CC * CC, bufB, sW, acc, tid);
#pragma unroll
        for (int p = 0; p < 4; ++p) {
            int o0 = opair(p, oL);
            float lo[8], hi[8];
#pragma unroll
            for (int j = 0; j < 8; ++j) unpack2(acc[p][j], lo[j], hi[j]);
            *(float4*)(skips + (size_t)o0 * TLEN + t0 + tL) =
                make_float4(lo[0], lo[1], lo[2], lo[3]);
            *(float4*)(skips + (size_t)o0 * TLEN + t0 + 64 + tL) =
                make_float4(lo[4], lo[5], lo[6], lo[7]);
            *(float4*)(skips + (size_t)(o0 + 1) * TLEN + t0 + tL) =
                make_float4(hi[0], hi[1], hi[2], hi[3]);
            *(float4*)(skips + (size_t)(o0 + 1) * TLEN + t0 + 64 + tL) =
                make_float4(hi[4], hi[5], hi[6], hi[7]);
        }
    }
}

// -------- host orchestration --------
extern "C" void kernel_launch(void* const* d_in, const int* in_sizes, int n_in,
                              void* d_out, int out_size)
{
    const float* x      = (const float*)d_in[0];
    const float* w_in   = (const float*)d_in[1];
    const float* b_in   = (const float*)d_in[2];
    const float* w_dil  = (const float*)d_in[3];
    const float* b_dil  = (const float*)d_in[4];
    const float* w_tanh = (const float*)d_in[5];
    const float* b_tanh = (const float*)d_in[6];
    const float* w_sig  = (const float*)d_in[7];
    const float* b_sig  = (const float*)d_in[8];
    const float* w_skip = (const float*)d_in[9];
    const float* b_skip = (const float*)d_in[10];
    float* out = (float*)d_out;

    cudaFuncSetAttribute(layer_kernel,
                         cudaFuncAttributeMaxDynamicSharedMemorySize, SMEM_BYTES);

    transpose_weights<<<(LL * CC * CC + 255) / 256, 256>>>(w_dil, w_tanh, w_sig, w_skip);
    input_conv<<<(BB * CC * TLEN / 4 + 255) / 256, 256>>>(x, w_in, b_in);

    const int dils[LL] = {1, 2, 4, 8, 16, 32, 64, 128, 256, 512,
                          1, 2, 4, 8, 16, 32, 64, 128, 256, 512};
    for (int i = 0; i < LL; ++i) {
        layer_kernel<<<(BB * TLEN) / TT, 256, SMEM_BYTES>>>(
            i, dils[i], i & 1, b_dil, b_tanh, b_sig, b_skip, out);
    }
}

// round 4
// speedup vs baseline: 2.6660x; 2.2884x over previous
#include <cuda_runtime.h>
#include <cuda_bf16.h>
#include <math.h>
#include <stdint.h>

#define CC   128
#define TLEN 8192
#define BB   2
#define LL   20
#define TT   128

// smem map (bytes)
#define SM_W0   0
#define SM_W1   32768
#define SM_ACT  65536
#define ACT_TILE 32768
#define SMEM_TOTAL (SM_ACT + 4 * ACT_TILE)   // 196608

// ---------------- device scratch ----------------
__device__ float g_h0[BB * CC * TLEN];
__device__ float g_h1[BB * CC * TLEN];
// weight images: [l][mat 0..4][hl 0..1][16384 bf16], swizzled [o][c] tile layout
__device__ __nv_bfloat16 g_wimg[LL * 5 * 2 * 16384];

// ---------------- helpers ----------------
__device__ __forceinline__ uint32_t smem_u32(const void* p) {
    uint32_t a;
    asm("{ .reg .u64 t; cvta.to.shared.u64 t, %1; cvt.u32.u64 %0, t; }" : "=r"(a) : "l"(p));
    return a;
}
// cvt.rn.bf16x2.f32 d, a, b : a -> high half, b -> low half
__device__ __forceinline__ uint32_t cvt_bf16x2(float hi, float lo) {
    uint32_t r; asm("cvt.rn.bf16x2.f32 %0, %1, %2;" : "=r"(r) : "f"(hi), "f"(lo)); return r;
}
__device__ __forceinline__ float bflo_f(uint32_t p) { return __uint_as_float(p << 16); }
__device__ __forceinline__ float bfhi_f(uint32_t p) { return __uint_as_float(p & 0xffff0000u); }

#define LDSM4(r, addr) \
    asm volatile("ldmatrix.sync.aligned.m8n8.x4.shared.b16 {%0,%1,%2,%3}, [%4];" \
        : "=r"((r)[0]), "=r"((r)[1]), "=r"((r)[2]), "=r"((r)[3]) : "r"(addr))
#define LDSM4T(r, addr) \
    asm volatile("ldmatrix.sync.aligned.m8n8.x4.trans.shared.b16 {%0,%1,%2,%3}, [%4];" \
        : "=r"((r)[0]), "=r"((r)[1]), "=r"((r)[2]), "=r"((r)[3]) : "r"(addr))
#define STSM4T(addr, r) \
    asm volatile("stmatrix.sync.aligned.m8n8.x4.trans.shared.b16 [%0], {%1,%2,%3,%4};" \
        :: "r"(addr), "r"((r)[0]), "r"((r)[1]), "r"((r)[2]), "r"((r)[3]))
#define MMA_BF16(d, a, b0, b1) \
    asm volatile("mma.sync.aligned.m16n8k16.row.col.f32.bf16.bf16.f32 " \
        "{%0,%1,%2,%3}, {%4,%5,%6,%7}, {%8,%9}, {%0,%1,%2,%3};" \
        : "+f"((d)[0]), "+f"((d)[1]), "+f"((d)[2]), "+f"((d)[3]) \
        : "r"((a)[0]), "r"((a)[1]), "r"((a)[2]), "r"((a)[3]), "r"(b0), "r"(b1))
#define CP_ASYNC16(saddr, gaddr) \
    asm volatile("cp.async.cg.shared.global [%0], [%1], 16;" :: "r"(saddr), "l"(gaddr))
#define CP_COMMIT() asm volatile("cp.async.commit_group;" ::: "memory")

__device__ __forceinline__ float sigmoidf_fast(float v) { return 1.0f / (1.0f + __expf(-v)); }
__device__ __forceinline__ float tanhf_fast(float v) {
    float a = fabsf(v);
    float e = __expf(-2.0f * a);
    float t = (1.0f - e) / (1.0f + e);
    return copysignf(t, v);
}

// ---------------- prep kernels ----------------
// tile layout byte(r, c) = r*256 + (((c>>3) ^ (r&7))<<4) + (c&7)*2   (r = row index, c = bf16 col)
__global__ void prep_weights(const float* __restrict__ w_dil,
                             const float* __restrict__ w_tanh,
                             const float* __restrict__ w_sig,
                             const float* __restrict__ w_skip)
{
    int idx = blockIdx.x * blockDim.x + threadIdx.x;
    if (idx >= LL * 5 * CC * CC) return;
    int k = idx & 127;
    int o = (idx >> 7) & 127;
    int m = (idx >> 14) % 5;
    int l = idx / (5 * CC * CC);
    size_t oc = ((size_t)l * CC + o) * CC + k;
    float v;
    if (m == 0)      v = w_dil[oc * 2 + 0];
    else if (m == 1) v = w_dil[oc * 2 + 1];
    else if (m == 2) v = w_tanh[oc];
    else if (m == 3) v = w_sig[oc];
    else             v = w_skip[oc];
    __nv_bfloat16 hi = __float2bfloat16(v);
    __nv_bfloat16 lo = __float2bfloat16(v - __bfloat162float(hi));
    uint32_t byte = (uint32_t)o * 256 + ((((uint32_t)(k >> 3)) ^ (o & 7)) << 4) + (k & 7) * 2;
    size_t base = ((size_t)(l * 5 + m) * 2) * 16384;
    g_wimg[base + (byte >> 1)]         = hi;
    g_wimg[base + 16384 + (byte >> 1)] = lo;
}

__global__ void input_conv(const float* __restrict__ x,
                           const float* __restrict__ w_in,
                           const float* __restrict__ b_in)
{
    int i4 = blockIdx.x * blockDim.x + threadIdx.x;
    if (i4 >= BB * CC * TLEN / 4) return;
    int t4 = i4 & (TLEN / 4 - 1);
    int c  = (i4 >> 11) & (CC - 1);
    int b  = i4 >> 18;
    float w = w_in[c], bv = b_in[c];
    float4 xv = ((const float4*)x)[(size_t)b * (TLEN / 4) + t4];
    float4 h;
    h.x = fmaf(w, xv.x, bv); h.y = fmaf(w, xv.y, bv);
    h.z = fmaf(w, xv.z, bv); h.w = fmaf(w, xv.w, bv);
    ((float4*)g_h0)[i4] = h;
}

// ---------------- mma term: acc += W(smem [o][c]) @ X(smem [t][c]) ----------------
__device__ __forceinline__ void mma_term(float (&acc)[2][8][4],
                                         uint32_t wA, uint32_t xB,
                                         uint32_t aoff, uint32_t boff,
                                         uint32_t lmask, uint32_t asel, uint32_t bsel)
{
#pragma unroll
    for (int ks = 0; ks < 8; ++ks) {
        uint32_t a0[4], a1[4];
        uint32_t acu = (((uint32_t)(2 * ks) + asel) << 4) ^ lmask;
        LDSM4(a0, wA + aoff + acu);
        LDSM4(a1, wA + aoff + 4096 + acu);
        uint32_t bcu = (((uint32_t)(2 * ks) + bsel) << 4) ^ lmask;
#pragma unroll
        for (int ntp = 0; ntp < 4; ++ntp) {
            uint32_t b[4];
            LDSM4(b, xB + boff + (uint32_t)ntp * 4096 + bcu);
            MMA_BF16(acc[0][2 * ntp],     a0, b[0], b[1]);
            MMA_BF16(acc[0][2 * ntp + 1], a0, b[2], b[3]);
            MMA_BF16(acc[1][2 * ntp],     a1, b[0], b[1]);
            MMA_BF16(acc[1][2 * ntp + 1], a1, b[2], b[3]);
        }
    }
}

// ---------------- fused layer kernel ----------------
__global__ void __launch_bounds__(256, 1)
layer_kernel(int layer, int dil, int ping,
             const float* __restrict__ b_dil, const float* __restrict__ b_tanh,
             const float* __restrict__ b_sig, const float* __restrict__ b_skip,
             float* __restrict__ out_base)
{
    extern __shared__ char smem[];
    const uint32_t sb = smem_u32(smem);
    const int tid = threadIdx.x;
    const int wid = tid >> 5, lane = tid & 31;
    const int wm = wid & 3, wn = wid >> 2;

    const float* hin  = ping ? g_h1 : g_h0;
    float*       hout = ping ? g_h0 : g_h1;
    const int blk = blockIdx.x;
    const int b   = blk >> 6;
    const int t0  = (blk & 63) * TT;
    const float* hbase = hin + (size_t)b * CC * TLEN;
    float* hob     = hout + (size_t)b * CC * TLEN;
    float* outputs = out_base + ((size_t)layer * BB + b) * CC * TLEN;
    float* skips   = out_base + (size_t)LL * BB * CC * TLEN + ((size_t)layer * BB + b) * CC * TLEN;

    // ---- prefetch first two weight images (w0h, w0l)
    {
        const char* g0 = (const char*)(g_wimg + ((size_t)(layer * 5 + 0) * 2 + 0) * 16384);
        const char* g1 = (const char*)(g_wimg + ((size_t)(layer * 5 + 0) * 2 + 1) * 16384);
#pragma unroll
        for (int j = 0; j < 8; ++j)
            CP_ASYNC16(sb + SM_W0 + tid * 16 + j * 4096, g0 + tid * 16 + j * 4096);
        CP_COMMIT();
#pragma unroll
        for (int j = 0; j < 8; ++j)
            CP_ASYNC16(sb + SM_W1 + tid * 16 + j * 4096, g1 + tid * 16 + j * 4096);
        CP_COMMIT();
    }

    // ---- stage acts: hcur -> tiles 0/1 (hi/lo), hdel -> tiles 2/3; fused outputs copy
    {
        const int t = tid & 127;
        const int chalf = tid >> 7;
        const uint32_t rowbase = (uint32_t)t * 256;
        const uint32_t rmask = (uint32_t)(t & 7);
        const float* hsrc = hbase + t0 + t;
        float* outp = outputs + t0 + t;
        const int tdel = t0 + t - dil;
        const float* dsrc = hbase + tdel;
        const bool dok = (tdel >= 0);
#pragma unroll 2
        for (int jb = 0; jb < 8; ++jb) {
            int cc0 = chalf * 64 + jb * 8;
            uint32_t hreg[4], lreg[4], dh[4], dl[4];
#pragma unroll
            for (int e = 0; e < 4; ++e) {
                float v0 = __ldg(hsrc + (size_t)(cc0 + 2 * e) * TLEN);
                float v1 = __ldg(hsrc + (size_t)(cc0 + 2 * e + 1) * TLEN);
                outp[(size_t)(cc0 + 2 * e) * TLEN]     = v0;
                outp[(size_t)(cc0 + 2 * e + 1) * TLEN] = v1;
                uint32_t h2 = cvt_bf16x2(v1, v0);
                hreg[e] = h2;
                lreg[e] = cvt_bf16x2(v1 - bfhi_f(h2), v0 - bflo_f(h2));
                float d0 = dok ? __ldg(dsrc + (size_t)(cc0 + 2 * e) * TLEN) : 0.0f;
                float d1 = dok ? __ldg(dsrc + (size_t)(cc0 + 2 * e + 1) * TLEN) : 0.0f;
                uint32_t dd = cvt_bf16x2(d1, d0);
                dh[e] = dd;
                dl[e] = cvt_bf16x2(d1 - bfhi_f(dd), d0 - bflo_f(dd));
            }
            uint32_t unit = (((uint32_t)(cc0 >> 3)) ^ rmask) << 4;
            char* base = smem + SM_ACT + rowbase + unit;
            *(uint4*)(base)                 = make_uint4(hreg[0], hreg[1], hreg[2], hreg[3]);
            *(uint4*)(base + ACT_TILE)      = make_uint4(lreg[0], lreg[1], lreg[2], lreg[3]);
            *(uint4*)(base + 2 * ACT_TILE)  = make_uint4(dh[0], dh[1], dh[2], dh[3]);
            *(uint4*)(base + 3 * ACT_TILE)  = make_uint4(dl[0], dl[1], dl[2], dl[3]);
        }
    }
    __syncthreads();

    // per-lane invariants
    const uint32_t lmask = (uint32_t)(lane & 7) << 4;
    const uint32_t asel = (uint32_t)((lane >> 4) & 1);
    const uint32_t bsel = (uint32_t)((lane >> 3) & 1);
    const uint32_t aoff = (uint32_t)(wm * 32 + (lane & 7) + ((lane >> 3) & 1) * 8) * 256;
    const uint32_t boff = (uint32_t)(wn * 64 + (lane & 7) + ((lane >> 4) & 1) * 8) * 256;
    // stmatrix/ldmatrix.trans per-mt unit offsets
    uint32_t sunit[2];
#pragma unroll
    for (int mt = 0; mt < 2; ++mt)
        sunit[mt] = (((uint32_t)(wm * 4 + mt * 2 + ((lane >> 3) & 1))) << 4) ^ lmask;

    float accA[2][8][4], accB[2][8][4];

    auto init_acc = [&](float (&A)[2][8][4], const float* bias) {
#pragma unroll
        for (int mt = 0; mt < 2; ++mt) {
            float v0 = __ldg(bias + wm * 32 + mt * 16 + (lane >> 2));
            float v1 = __ldg(bias + wm * 32 + mt * 16 + 8 + (lane >> 2));
#pragma unroll
            for (int nt = 0; nt < 8; ++nt) {
                A[mt][nt][0] = v0; A[mt][nt][1] = v0;
                A[mt][nt][2] = v1; A[mt][nt][3] = v1;
            }
        }
    };

    const int xsel_tab[5] = {2, 0, 0, 0, 2};   // act tile pair base per matrix

#pragma unroll 1
    for (int i = 0; i < 10; ++i) {
        if (i == 9) asm volatile("cp.async.wait_group 0;" ::: "memory");
        else        asm volatile("cp.async.wait_group 1;" ::: "memory");
        __syncthreads();

        if (i == 0) init_acc(accA, b_dil  + layer * CC);
        if (i == 4) init_acc(accA, b_tanh + layer * CC);
        if (i == 6) init_acc(accB, b_sig  + layer * CC);
        if (i == 8) init_acc(accA, b_skip + layer * CC);

        const int mat = i >> 1;
        const int hl  = i & 1;
        const uint32_t wA = sb + ((i & 1) ? SM_W1 : SM_W0);
        const uint32_t xH = sb + SM_ACT + (uint32_t)xsel_tab[mat] * ACT_TILE;
        const uint32_t xL = xH + ACT_TILE;
        const bool useB = (i == 6 || i == 7);

        if (useB) {
            mma_term(accB, wA, xH, aoff, boff, lmask, asel, bsel);
            if (hl == 0) mma_term(accB, wA, xL, aoff, boff, lmask, asel, bsel);
        } else {
            mma_term(accA, wA, xH, aoff, boff, lmask, asel, bsel);
            if (hl == 0) mma_term(accA, wA, xL, aoff, boff, lmask, asel, bsel);
        }

        // ---- epilogue 1: xdil -> tiles 0/1 (overwrite hcur)
        if (i == 3) {
            __syncthreads();
#pragma unroll
            for (int mt = 0; mt < 2; ++mt)
#pragma unroll
                for (int ntp = 0; ntp < 4; ++ntp) {
                    uint32_t rh[4], rl[4];
#pragma unroll
                    for (int q = 0; q < 4; ++q) {
                        float d0 = accA[mt][2 * ntp + (q >> 1)][(q & 1) * 2 + 0];
                        float d1 = accA[mt][2 * ntp + (q >> 1)][(q & 1) * 2 + 1];
                        uint32_t h = cvt_bf16x2(d1, d0);
                        rh[q] = h;
                        rl[q] = cvt_bf16x2(d1 - bfhi_f(h), d0 - bflo_f(h));
                    }
                    uint32_t ad = boff + (uint32_t)ntp * 4096 + sunit[mt];
                    STSM4T(sb + SM_ACT + ad, rh);
                    STSM4T(sb + SM_ACT + ACT_TILE + ad, rl);
                }
            __syncthreads();
        }

        // ---- epilogue 2: filt/gate -> xh (tiles 2/3), h_next -> global
        if (i == 7) {
            __syncthreads();
#pragma unroll
            for (int mt = 0; mt < 2; ++mt)
#pragma unroll
                for (int ntp = 0; ntp < 4; ++ntp) {
                    uint32_t ad = boff + (uint32_t)ntp * 4096 + sunit[mt];
                    uint32_t rh[4], rl[4];
                    LDSM4T(rh, sb + SM_ACT + ad);
                    LDSM4T(rl, sb + SM_ACT + ACT_TILE + ad);
                    uint32_t sh[4], sl[4];
#pragma unroll
                    for (int q = 0; q < 4; ++q) {
                        int nt = 2 * ntp + (q >> 1), hh = q & 1;
                        float xd0 = bflo_f(rh[q]) + bflo_f(rl[q]);
                        float xd1 = bfhi_f(rh[q]) + bfhi_f(rl[q]);
                        float f0 = tanhf_fast(accA[mt][nt][hh * 2 + 0]);
                        float f1 = tanhf_fast(accA[mt][nt][hh * 2 + 1]);
                        float g0 = sigmoidf_fast(accB[mt][nt][hh * 2 + 0]);
                        float g1 = sigmoidf_fast(accB[mt][nt][hh * 2 + 1]);
                        float xh0 = f0 * g0, xh1 = f1 * g1;
                        int o  = wm * 32 + mt * 16 + hh * 8 + (lane >> 2);
                        int tg = t0 + wn * 64 + nt * 8 + (lane & 3) * 2;
                        float2 hv = make_float2(xh0 + xd0, xh1 + xd1);
                        *(float2*)(hob + (size_t)o * TLEN + tg) = hv;
                        uint32_t h = cvt_bf16x2(xh1, xh0);
                        sh[q] = h;
                        sl[q] = cvt_bf16x2(xh1 - bfhi_f(h), xh0 - bflo_f(h));
                    }
                    STSM4T(sb + SM_ACT + 2 * ACT_TILE + ad, sh);
                    STSM4T(sb + SM_ACT + 3 * ACT_TILE + ad, sl);
                }
            __syncthreads();
        }

        // ---- epilogue 3: skip -> global
        if (i == 9) {
#pragma unroll
            for (int mt = 0; mt < 2; ++mt)
#pragma unroll
                for (int nt = 0; nt < 8; ++nt)
#pragma unroll
                    for (int hh = 0; hh < 2; ++hh) {
                        int o  = wm * 32 + mt * 16 + hh * 8 + (lane >> 2);
                        int tg = t0 + wn * 64 + nt * 8 + (lane & 3) * 2;
                        float2 sv = make_float2(accA[mt][nt][hh * 2 + 0],
                                                accA[mt][nt][hh * 2 + 1]);
                        *(float2*)(skips + (size_t)o * TLEN + tg) = sv;
                    }
        }

        __syncthreads();
        // prefetch weight image i+2 into the buffer we just finished
        if (i + 2 <= 9) {
            int ni = i + 2;
            const char* gsrc = (const char*)(g_wimg +
                ((size_t)(layer * 5 + (ni >> 1)) * 2 + (ni & 1)) * 16384);
            uint32_t dst = sb + ((ni & 1) ? SM_W1 : SM_W0);
#pragma unroll
            for (int j = 0; j < 8; ++j)
                CP_ASYNC16(dst + tid * 16 + j * 4096, gsrc + tid * 16 + j * 4096);
            CP_COMMIT();
        }
    }
}

// ---------------- host ----------------
extern "C" void kernel_launch(void* const* d_in, const int* in_sizes, int n_in,
                              void* d_out, int out_size)
{
    const float* x      = (const float*)d_in[0];
    const float* w_in   = (const float*)d_in[1];
    const float* b_in   = (const float*)d_in[2];
    const float* w_dil  = (const float*)d_in[3];
    const float* b_dil  = (const float*)d_in[4];
    const float* w_tanh = (const float*)d_in[5];
    const float* b_tanh = (const float*)d_in[6];
    const float* w_sig  = (const float*)d_in[7];
    const float* b_sig  = (const float*)d_in[8];
    const float* w_skip = (const float*)d_in[9];
    const float* b_skip = (const float*)d_in[10];
    float* out = (float*)d_out;

    cudaFuncSetAttribute(layer_kernel,
                         cudaFuncAttributeMaxDynamicSharedMemorySize, SMEM_TOTAL);

    prep_weights<<<(LL * 5 * CC * CC + 255) / 256, 256>>>(w_dil, w_tanh, w_sig, w_skip);
    input_conv<<<(BB * CC * TLEN / 4 + 255) / 256, 256>>>(x, w_in, b_in);

    const int dils[LL] = {1, 2, 4, 8, 16, 32, 64, 128, 256, 512,
                          1, 2, 4, 8, 16, 32, 64, 128, 256, 512};
    for (int i = 0; i < LL; ++i) {
        layer_kernel<<<(BB * TLEN) / TT, 256, SMEM_TOTAL>>>(
            i, dils[i], i & 1, b_dil, b_tanh, b_sig, b_skip, out);
    }
}

// round 5
// speedup vs baseline: 2.9795x; 1.1176x over previous
#include <cuda_runtime.h>
#include <cuda_bf16.h>
#include <math.h>
#include <stdint.h>

#define CC   128
#define TLEN 8192
#define BB   2
#define LL   20
#define TT   128

// smem map (bytes)
#define SM_W0   0
#define SM_W1   32768
#define SM_ACT  65536
#define ACT_TILE 32768
#define SMEM_TOTAL (SM_ACT + 4 * ACT_TILE)   // 196608

// ---------------- device scratch ----------------
__device__ float g_h0[BB * CC * TLEN];
__device__ float g_h1[BB * CC * TLEN];
// weight images: [l][mat 0..4][hl 0..1][16384 bf16], swizzled [o][c] tile layout
__device__ __nv_bfloat16 g_wimg[LL * 5 * 2 * 16384];

// ---------------- helpers ----------------
__device__ __forceinline__ uint32_t smem_u32(const void* p) {
    uint32_t a;
    asm("{ .reg .u64 t; cvta.to.shared.u64 t, %1; cvt.u32.u64 %0, t; }" : "=r"(a) : "l"(p));
    return a;
}
// cvt.rn.bf16x2.f32 d, a, b : a -> high half, b -> low half
__device__ __forceinline__ uint32_t cvt_bf16x2(float hi, float lo) {
    uint32_t r; asm("cvt.rn.bf16x2.f32 %0, %1, %2;" : "=r"(r) : "f"(hi), "f"(lo)); return r;
}
__device__ __forceinline__ float bflo_f(uint32_t p) { return __uint_as_float(p << 16); }
__device__ __forceinline__ float bfhi_f(uint32_t p) { return __uint_as_float(p & 0xffff0000u); }

#define LDSM4(r, addr) \
    asm volatile("ldmatrix.sync.aligned.m8n8.x4.shared.b16 {%0,%1,%2,%3}, [%4];" \
        : "=r"((r)[0]), "=r"((r)[1]), "=r"((r)[2]), "=r"((r)[3]) : "r"(addr))
#define LDSM4T(r, addr) \
    asm volatile("ldmatrix.sync.aligned.m8n8.x4.trans.shared.b16 {%0,%1,%2,%3}, [%4];" \
        : "=r"((r)[0]), "=r"((r)[1]), "=r"((r)[2]), "=r"((r)[3]) : "r"(addr))
#define STSM4T(addr, r) \
    asm volatile("stmatrix.sync.aligned.m8n8.x4.trans.shared.b16 [%0], {%1,%2,%3,%4};" \
        :: "r"(addr), "r"((r)[0]), "r"((r)[1]), "r"((r)[2]), "r"((r)[3]))
#define MMA_BF16(d, a, b0, b1) \
    asm volatile("mma.sync.aligned.m16n8k16.row.col.f32.bf16.bf16.f32 " \
        "{%0,%1,%2,%3}, {%4,%5,%6,%7}, {%8,%9}, {%0,%1,%2,%3};" \
        : "+f"((d)[0]), "+f"((d)[1]), "+f"((d)[2]), "+f"((d)[3]) \
        : "r"((a)[0]), "r"((a)[1]), "r"((a)[2]), "r"((a)[3]), "r"(b0), "r"(b1))
#define CP_ASYNC16(saddr, gaddr) \
    asm volatile("cp.async.cg.shared.global [%0], [%1], 16;" :: "r"(saddr), "l"(gaddr))
#define CP_COMMIT() asm volatile("cp.async.commit_group;" ::: "memory")

__device__ __forceinline__ float sigmoidf_fast(float v) { return 1.0f / (1.0f + __expf(-v)); }
__device__ __forceinline__ float tanhf_fast(float v) {
    float a = fabsf(v);
    float e = __expf(-2.0f * a);
    float t = (1.0f - e) / (1.0f + e);
    return copysignf(t, v);
}

// ---------------- prep kernels ----------------
// tile layout byte(r, c) = r*256 + (((c>>3) ^ (r&7))<<4) + (c&7)*2   (r = row index, c = bf16 col)
__global__ void prep_weights(const float* __restrict__ w_dil,
                             const float* __restrict__ w_tanh,
                             const float* __restrict__ w_sig,
                             const float* __restrict__ w_skip)
{
    int idx = blockIdx.x * blockDim.x + threadIdx.x;
    if (idx >= LL * 5 * CC * CC) return;
    int k = idx & 127;
    int o = (idx >> 7) & 127;
    int m = (idx >> 14) % 5;
    int l = idx / (5 * CC * CC);
    size_t oc = ((size_t)l * CC + o) * CC + k;
    float v;
    if (m == 0)      v = w_dil[oc * 2 + 0];
    else if (m == 1) v = w_dil[oc * 2 + 1];
    else if (m == 2) v = w_tanh[oc];
    else if (m == 3) v = w_sig[oc];
    else             v = w_skip[oc];
    __nv_bfloat16 hi = __float2bfloat16(v);
    __nv_bfloat16 lo = __float2bfloat16(v - __bfloat162float(hi));
    uint32_t byte = (uint32_t)o * 256 + ((((uint32_t)(k >> 3)) ^ (o & 7)) << 4) + (k & 7) * 2;
    size_t base = ((size_t)(l * 5 + m) * 2) * 16384;
    g_wimg[base + (byte >> 1)]         = hi;
    g_wimg[base + 16384 + (byte >> 1)] = lo;
}

__global__ void input_conv(const float* __restrict__ x,
                           const float* __restrict__ w_in,
                           const float* __restrict__ b_in)
{
    int i4 = blockIdx.x * blockDim.x + threadIdx.x;
    if (i4 >= BB * CC * TLEN / 4) return;
    int t4 = i4 & (TLEN / 4 - 1);
    int c  = (i4 >> 11) & (CC - 1);
    int b  = i4 >> 18;
    float w = w_in[c], bv = b_in[c];
    float4 xv = ((const float4*)x)[(size_t)b * (TLEN / 4) + t4];
    float4 h;
    h.x = fmaf(w, xv.x, bv); h.y = fmaf(w, xv.y, bv);
    h.z = fmaf(w, xv.z, bv); h.w = fmaf(w, xv.w, bv);
    ((float4*)g_h0)[i4] = h;
}

// ---------------- mma term: acc += W(smem [o][c]) @ X(smem [t][c]) ----------------
// 16-warp variant: per warp M=32 (2 mt), N=32 (2 ntp of 16 t)
__device__ __forceinline__ void mma_term(float (&acc)[2][4][4],
                                         uint32_t wA, uint32_t xB,
                                         uint32_t aoff, uint32_t boff,
                                         uint32_t lmask, uint32_t asel, uint32_t bsel)
{
#pragma unroll
    for (int ks = 0; ks < 8; ++ks) {
        uint32_t a0[4], a1[4];
        uint32_t acu = (((uint32_t)(2 * ks) + asel) << 4) ^ lmask;
        LDSM4(a0, wA + aoff + acu);
        LDSM4(a1, wA + aoff + 4096 + acu);
        uint32_t bcu = (((uint32_t)(2 * ks) + bsel) << 4) ^ lmask;
#pragma unroll
        for (int ntp = 0; ntp < 2; ++ntp) {
            uint32_t b[4];
            LDSM4(b, xB + boff + (uint32_t)ntp * 4096 + bcu);
            MMA_BF16(acc[0][2 * ntp],     a0, b[0], b[1]);
            MMA_BF16(acc[0][2 * ntp + 1], a0, b[2], b[3]);
            MMA_BF16(acc[1][2 * ntp],     a1, b[0], b[1]);
            MMA_BF16(acc[1][2 * ntp + 1], a1, b[2], b[3]);
        }
    }
}

// ---------------- fused layer kernel ----------------
__global__ void __launch_bounds__(512, 1)
layer_kernel(int layer, int dil, int ping,
             const float* __restrict__ b_dil, const float* __restrict__ b_tanh,
             const float* __restrict__ b_sig, const float* __restrict__ b_skip,
             float* __restrict__ out_base)
{
    extern __shared__ char smem[];
    const uint32_t sb = smem_u32(smem);
    const int tid = threadIdx.x;
    const int wid = tid >> 5, lane = tid & 31;
    const int wm = wid & 3, wn = wid >> 2;     // wm 0..3 (o), wn 0..3 (t, 32 each)

    const float* hin  = ping ? g_h1 : g_h0;
    float*       hout = ping ? g_h0 : g_h1;
    const int blk = blockIdx.x;
    const int b   = blk >> 6;
    const int t0  = (blk & 63) * TT;
    const float* hbase = hin + (size_t)b * CC * TLEN;
    float* hob     = hout + (size_t)b * CC * TLEN;
    float* outputs = out_base + ((size_t)layer * BB + b) * CC * TLEN;
    float* skips   = out_base + (size_t)LL * BB * CC * TLEN + ((size_t)layer * BB + b) * CC * TLEN;

    // ---- prefetch first two weight images (w0h, w0l): 32768 B each, 512 thr * 16 B = 8192/j
    {
        const char* g0 = (const char*)(g_wimg + ((size_t)(layer * 5 + 0) * 2 + 0) * 16384);
        const char* g1 = (const char*)(g_wimg + ((size_t)(layer * 5 + 0) * 2 + 1) * 16384);
#pragma unroll
        for (int j = 0; j < 4; ++j)
            CP_ASYNC16(sb + SM_W0 + tid * 16 + j * 8192, g0 + tid * 16 + j * 8192);
        CP_COMMIT();
#pragma unroll
        for (int j = 0; j < 4; ++j)
            CP_ASYNC16(sb + SM_W1 + tid * 16 + j * 8192, g1 + tid * 16 + j * 8192);
        CP_COMMIT();
    }

    // ---- stage acts: hcur -> tiles 0/1 (hi/lo), hdel -> tiles 2/3; fused outputs copy
    {
        const int t = tid & 127;
        const int quar = tid >> 7;              // 0..3, 32 channels each
        const uint32_t rowbase = (uint32_t)t * 256;
        const uint32_t rmask = (uint32_t)(t & 7);
        const float* hsrc = hbase + t0 + t;
        float* outp = outputs + t0 + t;
        const int tdel = t0 + t - dil;
        const float* dsrc = hbase + tdel;
        const bool dok = (tdel >= 0);
#pragma unroll 2
        for (int jb = 0; jb < 4; ++jb) {
            int cc0 = quar * 32 + jb * 8;
            uint32_t hreg[4], lreg[4], dh[4], dl[4];
#pragma unroll
            for (int e = 0; e < 4; ++e) {
                float v0 = __ldg(hsrc + (size_t)(cc0 + 2 * e) * TLEN);
                float v1 = __ldg(hsrc + (size_t)(cc0 + 2 * e + 1) * TLEN);
                outp[(size_t)(cc0 + 2 * e) * TLEN]     = v0;
                outp[(size_t)(cc0 + 2 * e + 1) * TLEN] = v1;
                uint32_t h2 = cvt_bf16x2(v1, v0);
                hreg[e] = h2;
                lreg[e] = cvt_bf16x2(v1 - bfhi_f(h2), v0 - bflo_f(h2));
                float d0 = dok ? __ldg(dsrc + (size_t)(cc0 + 2 * e) * TLEN) : 0.0f;
                float d1 = dok ? __ldg(dsrc + (size_t)(cc0 + 2 * e + 1) * TLEN) : 0.0f;
                uint32_t dd = cvt_bf16x2(d1, d0);
                dh[e] = dd;
                dl[e] = cvt_bf16x2(d1 - bfhi_f(dd), d0 - bflo_f(dd));
            }
            uint32_t unit = (((uint32_t)(cc0 >> 3)) ^ rmask) << 4;
            char* base = smem + SM_ACT + rowbase + unit;
            *(uint4*)(base)                 = make_uint4(hreg[0], hreg[1], hreg[2], hreg[3]);
            *(uint4*)(base + ACT_TILE)      = make_uint4(lreg[0], lreg[1], lreg[2], lreg[3]);
            *(uint4*)(base + 2 * ACT_TILE)  = make_uint4(dh[0], dh[1], dh[2], dh[3]);
            *(uint4*)(base + 3 * ACT_TILE)  = make_uint4(dl[0], dl[1], dl[2], dl[3]);
        }
    }
    __syncthreads();

    // per-lane invariants
    const uint32_t lmask = (uint32_t)(lane & 7) << 4;
    const uint32_t asel = (uint32_t)((lane >> 4) & 1);
    const uint32_t bsel = (uint32_t)((lane >> 3) & 1);
    const uint32_t aoff = (uint32_t)(wm * 32 + (lane & 7) + ((lane >> 3) & 1) * 8) * 256;
    const uint32_t boff = (uint32_t)(wn * 32 + (lane & 7) + ((lane >> 4) & 1) * 8) * 256;
    // stmatrix/ldmatrix.trans per-mt unit offsets
    uint32_t sunit[2];
#pragma unroll
    for (int mt = 0; mt < 2; ++mt)
        sunit[mt] = (((uint32_t)(wm * 4 + mt * 2 + ((lane >> 3) & 1))) << 4) ^ lmask;

    float accA[2][4][4], accB[2][4][4];

    auto init_acc = [&](float (&A)[2][4][4], const float* bias) {
#pragma unroll
        for (int mt = 0; mt < 2; ++mt) {
            float v0 = __ldg(bias + wm * 32 + mt * 16 + (lane >> 2));
            float v1 = __ldg(bias + wm * 32 + mt * 16 + 8 + (lane >> 2));
#pragma unroll
            for (int nt = 0; nt < 4; ++nt) {
                A[mt][nt][0] = v0; A[mt][nt][1] = v0;
                A[mt][nt][2] = v1; A[mt][nt][3] = v1;
            }
        }
    };

    const int xsel_tab[5] = {2, 0, 0, 0, 2};   // act tile pair base per matrix

#pragma unroll 1
    for (int i = 0; i < 10; ++i) {
        if (i == 9) asm volatile("cp.async.wait_group 0;" ::: "memory");
        else        asm volatile("cp.async.wait_group 1;" ::: "memory");
        __syncthreads();

        if (i == 0) init_acc(accA, b_dil  + layer * CC);
        if (i == 4) init_acc(accA, b_tanh + layer * CC);
        if (i == 6) init_acc(accB, b_sig  + layer * CC);
        if (i == 8) init_acc(accA, b_skip + layer * CC);

        const int mat = i >> 1;
        const int hl  = i & 1;
        const uint32_t wA = sb + ((i & 1) ? SM_W1 : SM_W0);
        const uint32_t xH = sb + SM_ACT + (uint32_t)xsel_tab[mat] * ACT_TILE;
        const uint32_t xL = xH + ACT_TILE;
        const bool useB = (i == 6 || i == 7);

        if (useB) {
            mma_term(accB, wA, xH, aoff, boff, lmask, asel, bsel);
            if (hl == 0) mma_term(accB, wA, xL, aoff, boff, lmask, asel, bsel);
        } else {
            mma_term(accA, wA, xH, aoff, boff, lmask, asel, bsel);
            if (hl == 0) mma_term(accA, wA, xL, aoff, boff, lmask, asel, bsel);
        }

        // ---- epilogue 1: xdil -> tiles 0/1 (overwrite hcur)
        if (i == 3) {
            __syncthreads();
#pragma unroll
            for (int mt = 0; mt < 2; ++mt)
#pragma unroll
                for (int ntp = 0; ntp < 2; ++ntp) {
                    uint32_t rh[4], rl[4];
#pragma unroll
                    for (int q = 0; q < 4; ++q) {
                        float d0 = accA[mt][2 * ntp + (q >> 1)][(q & 1) * 2 + 0];
                        float d1 = accA[mt][2 * ntp + (q >> 1)][(q & 1) * 2 + 1];
                        uint32_t h = cvt_bf16x2(d1, d0);
                        rh[q] = h;
                        rl[q] = cvt_bf16x2(d1 - bfhi_f(h), d0 - bflo_f(h));
                    }
                    uint32_t ad = boff + (uint32_t)ntp * 4096 + sunit[mt];
                    STSM4T(sb + SM_ACT + ad, rh);
                    STSM4T(sb + SM_ACT + ACT_TILE + ad, rl);
                }
            __syncthreads();
        }

        // ---- epilogue 2: filt/gate -> xh (tiles 2/3), h_next -> global
        if (i == 7) {
            __syncthreads();
#pragma unroll
            for (int mt = 0; mt < 2; ++mt)
#pragma unroll
                for (int ntp = 0; ntp < 2; ++ntp) {
                    uint32_t ad = boff + (uint32_t)ntp * 4096 + sunit[mt];
                    uint32_t rh[4], rl[4];
                    LDSM4T(rh, sb + SM_ACT + ad);
                    LDSM4T(rl, sb + SM_ACT + ACT_TILE + ad);
                    uint32_t sh[4], sl[4];
#pragma unroll
                    for (int q = 0; q < 4; ++q) {
                        int nt = 2 * ntp + (q >> 1), hh = q & 1;
                        float xd0 = bflo_f(rh[q]) + bflo_f(rl[q]);
                        float xd1 = bfhi_f(rh[q]) + bfhi_f(rl[q]);
                        float f0 = tanhf_fast(accA[mt][nt][hh * 2 + 0]);
                        float f1 = tanhf_fast(accA[mt][nt][hh * 2 + 1]);
                        float g0 = sigmoidf_fast(accB[mt][nt][hh * 2 + 0]);
                        float g1 = sigmoidf_fast(accB[mt][nt][hh * 2 + 1]);
                        float xh0 = f0 * g0, xh1 = f1 * g1;
                        int o  = wm * 32 + mt * 16 + hh * 8 + (lane >> 2);
                        int tg = t0 + wn * 32 + nt * 8 + (lane & 3) * 2;
                        float2 hv = make_float2(xh0 + xd0, xh1 + xd1);
                        *(float2*)(hob + (size_t)o * TLEN + tg) = hv;
                        uint32_t h = cvt_bf16x2(xh1, xh0);
                        sh[q] = h;
                        sl[q] = cvt_bf16x2(xh1 - bfhi_f(h), xh0 - bflo_f(h));
                    }
                    STSM4T(sb + SM_ACT + 2 * ACT_TILE + ad, sh);
                    STSM4T(sb + SM_ACT + 3 * ACT_TILE + ad, sl);
                }
            __syncthreads();
        }

        // ---- epilogue 3: skip -> global
        if (i == 9) {
#pragma unroll
            for (int mt = 0; mt < 2; ++mt)
#pragma unroll
                for (int nt = 0; nt < 4; ++nt)
#pragma unroll
                    for (int hh = 0; hh < 2; ++hh) {
                        int o  = wm * 32 + mt * 16 + hh * 8 + (lane >> 2);
                        int tg = t0 + wn * 32 + nt * 8 + (lane & 3) * 2;
                        float2 sv = make_float2(accA[mt][nt][hh * 2 + 0],
                                                accA[mt][nt][hh * 2 + 1]);
                        *(float2*)(skips + (size_t)o * TLEN + tg) = sv;
                    }
        }

        __syncthreads();
        // prefetch weight image i+2 into the buffer we just finished
        if (i + 2 <= 9) {
            int ni = i + 2;
            const char* gsrc = (const char*)(g_wimg +
                ((size_t)(layer * 5 + (ni >> 1)) * 2 + (ni & 1)) * 16384);
            uint32_t dst = sb + ((ni & 1) ? SM_W1 : SM_W0);
#pragma unroll
            for (int j = 0; j < 4; ++j)
                CP_ASYNC16(dst + tid * 16 + j * 8192, gsrc + tid * 16 + j * 8192);
            CP_COMMIT();
        }
    }
}

// ---------------- host ----------------
extern "C" void kernel_launch(void* const* d_in, const int* in_sizes, int n_in,
                              void* d_out, int out_size)
{
    const float* x      = (const float*)d_in[0];
    const float* w_in   = (const float*)d_in[1];
    const float* b_in   = (const float*)d_in[2];
    const float* w_dil  = (const float*)d_in[3];
    const float* b_dil  = (const float*)d_in[4];
    const float* w_tanh = (const float*)d_in[5];
    const float* b_tanh = (const float*)d_in[6];
    const float* w_sig  = (const float*)d_in[7];
    const float* b_sig  = (const float*)d_in[8];
    const float* w_skip = (const float*)d_in[9];
    const float* b_skip = (const float*)d_in[10];
    float* out = (float*)d_out;

    cudaFuncSetAttribute(layer_kernel,
                         cudaFuncAttributeMaxDynamicSharedMemorySize, SMEM_TOTAL);

    prep_weights<<<(LL * 5 * CC * CC + 255) / 256, 256>>>(w_dil, w_tanh, w_sig, w_skip);
    input_conv<<<(BB * CC * TLEN / 4 + 255) / 256, 256>>>(x, w_in, b_in);

    const int dils[LL] = {1, 2, 4, 8, 16, 32, 64, 128, 256, 512,
                          1, 2, 4, 8, 16, 32, 64, 128, 256, 512};
    for (int i = 0; i < LL; ++i) {
        layer_kernel<<<(BB * TLEN) / TT, 512, SMEM_TOTAL>>>(
            i, dils[i], i & 1, b_dil, b_tanh, b_sig, b_skip, out);
    }
}